// round 3
// baseline (speedup 1.0000x reference)
#include <cuda_runtime.h>
#include <cuda_bf16.h>

// out[i][j] = support[2i+1][2j+1], support: 8192x8192 fp32, out: 4096x4096 fp32.
//
// One thread per 2x float4 of output (8 output elements). Each thread issues
// four independent float4 (16B) coalesced loads from input row 2*row+1 and two
// float4 (16B) coalesced stores. Pure memory-bound: ~128MB read + 64MB write
// (even input rows never touched).

#define IN_N   8192
#define OUT_N  4096
#define IN_F4  (IN_N / 4)               // 2048 float4 per input row
#define OUT_F4 (OUT_N / 4)              // 1024 float4 per output row
#define PAIRS_PER_ROW (OUT_F4 / 2)      // 512 thread-work-items per output row
#define TOTAL  (OUT_N * PAIRS_PER_ROW)  // 2M threads

__global__ __launch_bounds__(256) void downsample_odd_kernel(
    const float4* __restrict__ in, float4* __restrict__ out)
{
    unsigned idx = blockIdx.x * 256u + threadIdx.x;

    unsigned row  = idx >> 9;           // / PAIRS_PER_ROW (512)
    unsigned pair = idx & 511u;         // % PAIRS_PER_ROW

    // Input row 2*row+1. This thread produces output float4 indices
    // 2*pair and 2*pair+1, consuming input float4 indices 4*pair .. 4*pair+3.
    const float4* src = in + (size_t)(2u * row + 1u) * IN_F4 + 4u * pair;
    float4 a = __ldg(src + 0);
    float4 b = __ldg(src + 1);
    float4 c = __ldg(src + 2);
    float4 d = __ldg(src + 3);

    float4* dst = out + (size_t)row * OUT_F4 + 2u * pair;
    dst[0] = make_float4(a.y, a.w, b.y, b.w);
    dst[1] = make_float4(c.y, c.w, d.y, d.w);
}

extern "C" void kernel_launch(void* const* d_in, const int* in_sizes, int n_in,
                              void* d_out, int out_size)
{
    const float4* in = (const float4*)d_in[0];
    float4* out = (float4*)d_out;

    unsigned blocks = TOTAL / 256;      // 8192, exact division
    downsample_odd_kernel<<<blocks, 256>>>(in, out);
}

// round 8
// speedup vs baseline: 1.1998x; 1.1998x over previous
#include <cuda_runtime.h>
#include <cuda_bf16.h>

// out[i][j] = support[2i+1][2j+1], support: 8192x8192 fp32, out: 4096x4096 fp32.
//
// Warp-strided layout: each block owns a contiguous 1024-float4 chunk of one
// odd input row (half a row). Thread t loads chunk[t + k*256] for k=0..3 —
// every LDG.128 is lane-contiguous (512B/warp, 4 wavefronts, minimal L1
// traffic). Each input float4 (cols 4j..4j+3) produces one output float2
// (odd cols 4j+1, 4j+3), stored lane-contiguously as STG.64 (256B/warp).
//
// Traffic: 128MB read (odd rows only; stride-2 fp32 touches every 32B sector)
// + 64MB write.

#define IN_N   8192
#define OUT_N  4096
#define IN_F4  (IN_N / 4)      // 2048 float4 per input row
#define OUT_F2 (OUT_N / 2)     // 2048 float2 per output row
#define CHUNK  1024            // input float4s per block (half an input row)

__global__ __launch_bounds__(256) void downsample_odd_kernel(
    const float4* __restrict__ in, float2* __restrict__ out)
{
    unsigned b   = blockIdx.x;
    unsigned row = b >> 1;                 // output row (input row 2*row+1)
    unsigned h   = b & 1u;                 // which half of the row

    unsigned base_j = h * CHUNK;           // float4 index within the row
    const float4* src = in + (size_t)(2u * row + 1u) * IN_F4 + base_j;
    float2*       dst = out + (size_t)row * OUT_F2 + base_j;

    unsigned t = threadIdx.x;

    // 4 independent lane-contiguous loads, front-batched for MLP.
    float4 v[4];
#pragma unroll
    for (int k = 0; k < 4; k++)
        v[k] = __ldg(src + t + k * 256);

#pragma unroll
    for (int k = 0; k < 4; k++)
        dst[t + k * 256] = make_float2(v[k].y, v[k].w);
}

extern "C" void kernel_launch(void* const* d_in, const int* in_sizes, int n_in,
                              void* d_out, int out_size)
{
    const float4* in = (const float4*)d_in[0];
    float2* out = (float2*)d_out;

    // 4096 output rows * 2 half-rows = 8192 blocks
    downsample_odd_kernel<<<8192, 256>>>(in, out);
}

// round 9
// speedup vs baseline: 1.2347x; 1.0291x over previous
#include <cuda_runtime.h>
#include <cuda_bf16.h>

// out[i][j] = support[2i+1][2j+1], support: 8192x8192 fp32, out: 4096x4096 fp32.
//
// One block per output row (4096 blocks). Thread t handles float4 indices
// t + k*256, k=0..7 of input row 2*row+1 — all loads lane-contiguous
// (512B/warp per LDG.128, minimum 4 L1 wavefronts), 8-deep front-batched MLP.
// Each input float4 (cols 4j..4j+3) yields one output float2 (odd cols
// 4j+1, 4j+3), stored lane-contiguously (256B/warp STG.64).
//
// Single-touch streaming data: __ldcs / __stcs evict-first hints keep L2 from
// retaining dead lines. Traffic: 128MB read (odd rows only) + 64MB write.

#define IN_N   8192
#define OUT_N  4096
#define IN_F4  (IN_N / 4)      // 2048 float4 per input row
#define OUT_F2 (OUT_N / 2)     // 2048 float2 per output row

__global__ __launch_bounds__(256) void downsample_odd_kernel(
    const float4* __restrict__ in, float2* __restrict__ out)
{
    unsigned row = blockIdx.x;             // output row (input row 2*row+1)
    unsigned t   = threadIdx.x;

    const float4* src = in + (size_t)(2u * row + 1u) * IN_F4;
    float2*       dst = out + (size_t)row * OUT_F2;

    // 8 independent lane-contiguous streaming loads, front-batched for MLP.
    float4 v[8];
#pragma unroll
    for (int k = 0; k < 8; k++)
        v[k] = __ldcs(src + t + k * 256);

#pragma unroll
    for (int k = 0; k < 8; k++)
        __stcs(dst + t + k * 256, make_float2(v[k].y, v[k].w));
}

extern "C" void kernel_launch(void* const* d_in, const int* in_sizes, int n_in,
                              void* d_out, int out_size)
{
    const float4* in = (const float4*)d_in[0];
    float2* out = (float2*)d_out;

    // one block per output row
    downsample_odd_kernel<<<4096, 256>>>(in, out);
}

// round 15
// speedup vs baseline: 1.2613x; 1.0215x over previous
#include <cuda_runtime.h>
#include <cuda_bf16.h>

// out[i][j] = support[2i+1][2j+1], support: 8192x8192 fp32, out: 4096x4096 fp32.
//
// R8 layout (best measured DRAM%: 78.9) + streaming cache hints.
// Each block owns a contiguous 1024-float4 chunk of one odd input row (half a
// row). Thread t loads chunk[t + k*256], k=0..3 — lane-contiguous LDG.128
// (512B/warp, minimum 4 L1 wavefronts), 4-deep front-batched MLP. Each input
// float4 (cols 4j..4j+3) yields one output float2 (odd cols 4j+1, 4j+3),
// stored lane-contiguously (256B/warp STG.64). Single-touch data -> evict-
// first (-cs) on both loads and stores.
//
// Traffic: 128MB read (odd rows only) + 64MB write = 192MB, HBM-bound.

#define IN_N   8192
#define OUT_N  4096
#define IN_F4  (IN_N / 4)      // 2048 float4 per input row
#define OUT_F2 (OUT_N / 2)     // 2048 float2 per output row
#define CHUNK  1024            // input float4s per block (half an input row)

__global__ __launch_bounds__(256) void downsample_odd_kernel(
    const float4* __restrict__ in, float2* __restrict__ out)
{
    unsigned b   = blockIdx.x;
    unsigned row = b >> 1;                 // output row (input row 2*row+1)
    unsigned h   = b & 1u;                 // which half of the row

    unsigned base_j = h * CHUNK;           // float4 index within the row
    const float4* src = in + (size_t)(2u * row + 1u) * IN_F4 + base_j;
    float2*       dst = out + (size_t)row * OUT_F2 + base_j;

    unsigned t = threadIdx.x;

    // 4 independent lane-contiguous streaming loads, front-batched for MLP.
    float4 v[4];
#pragma unroll
    for (int k = 0; k < 4; k++)
        v[k] = __ldcs(src + t + k * 256);

#pragma unroll
    for (int k = 0; k < 4; k++)
        __stcs(dst + t + k * 256, make_float2(v[k].y, v[k].w));
}

extern "C" void kernel_launch(void* const* d_in, const int* in_sizes, int n_in,
                              void* d_out, int out_size)
{
    const float4* in = (const float4*)d_in[0];
    float2* out = (float2*)d_out;

    // 4096 output rows * 2 half-rows = 8192 blocks
    downsample_odd_kernel<<<8192, 256>>>(in, out);
}

// round 16
// speedup vs baseline: 1.2626x; 1.0010x over previous
#include <cuda_runtime.h>
#include <cuda_bf16.h>

// out[i][j] = support[2i+1][2j+1], support: 8192x8192 fp32, out: 4096x4096 fp32.
//
// CONVERGED CONFIG (confirmation run). Each block owns a contiguous
// 1024-float4 chunk of one odd input row (half a row). Thread t loads
// chunk[t + k*256], k=0..3 — lane-contiguous LDG.128 (512B/warp, minimum 4 L1
// wavefronts), 4-deep front-batched MLP. Each input float4 (cols 4j..4j+3)
// yields one output float2 (odd cols 4j+1, 4j+3), stored lane-contiguously
// (256B/warp STG.64). Evict-first (-cs) on both sides (measured neutral).
//
// Traffic: 128MB read (odd rows only; odd cols touch every 32B sector, so the
// read is irreducible) + 64MB write = 192MB. Measured 6.0-6.2 TB/s across all
// tested configs -> HBM-bound at the practical ceiling for a 2:1 R/W stream.

#define IN_N   8192
#define OUT_N  4096
#define IN_F4  (IN_N / 4)      // 2048 float4 per input row
#define OUT_F2 (OUT_N / 2)     // 2048 float2 per output row
#define CHUNK  1024            // input float4s per block (half an input row)

__global__ __launch_bounds__(256) void downsample_odd_kernel(
    const float4* __restrict__ in, float2* __restrict__ out)
{
    unsigned b   = blockIdx.x;
    unsigned row = b >> 1;                 // output row (input row 2*row+1)
    unsigned h   = b & 1u;                 // which half of the row

    unsigned base_j = h * CHUNK;           // float4 index within the row
    const float4* src = in + (size_t)(2u * row + 1u) * IN_F4 + base_j;
    float2*       dst = out + (size_t)row * OUT_F2 + base_j;

    unsigned t = threadIdx.x;

    // 4 independent lane-contiguous streaming loads, front-batched for MLP.
    float4 v[4];
#pragma unroll
    for (int k = 0; k < 4; k++)
        v[k] = __ldcs(src + t + k * 256);

#pragma unroll
    for (int k = 0; k < 4; k++)
        __stcs(dst + t + k * 256, make_float2(v[k].y, v[k].w));
}

extern "C" void kernel_launch(void* const* d_in, const int* in_sizes, int n_in,
                              void* d_out, int out_size)
{
    const float4* in = (const float4*)d_in[0];
    float2* out = (float2*)d_out;

    // 4096 output rows * 2 half-rows = 8192 blocks
    downsample_odd_kernel<<<8192, 256>>>(in, out);
}